// round 11
// baseline (speedup 1.0000x reference)
#include <cuda_runtime.h>

// noiseRNN: h_t = tanh(W_ih x_t + b_ih + W_hh h_{t-1} + b_hh); carry h_t + 0.1*noise_t
// T=2048, B=256, I=64, H=128.
// R11: 256 blocks x 256 threads, ONE batch per block, __launch_bounds__(256,2)
// -> 2 independent CTAs (barrier domains) per SM so each CTA's serial
// reduce/tanh/barrier tail hides under the other CTA's FMA stream.
// Structure per CTA otherwise = R10: W in registers (4j x 24k per thread, 48
// packed f32x2), z=[h;x] broadcast from SMEM, f32x2 FMAs, SMEM partial reduce,
// depth-4 register prefetch ring for noise (reducers) and x (stagers).

#define T_STEPS 2048
#define BATCH   256
#define IN_DIM  64
#define HID     128
#define KDIM    192           // HID + IN_DIM
#define STD_F   0.1f

#define NWARPS  8
#define KSLICE  24            // KDIM / NWARPS
#define THREADS 256
#define NP      4             // prefetch pipeline depth (T_STEPS % NP == 0)

__device__ __forceinline__ unsigned long long fma2(unsigned long long a,
                                                   unsigned long long b,
                                                   unsigned long long c) {
    unsigned long long d;
    asm("fma.rn.f32x2 %0, %1, %2, %3;" : "=l"(d) : "l"(a), "l"(b), "l"(c));
    return d;
}
__device__ __forceinline__ unsigned long long packf2(float lo, float hi) {
    return (unsigned long long)__float_as_uint(lo) |
           ((unsigned long long)__float_as_uint(hi) << 32);
}
__device__ __forceinline__ float lo_f(unsigned long long v) {
    return __uint_as_float((unsigned)v);
}
__device__ __forceinline__ float hi_f(unsigned long long v) {
    return __uint_as_float((unsigned)(v >> 32));
}
// tanh(s) = 1 - 2/(exp(2s)+1): 2 MUFU + 4 fp ops, ~1e-6 accuracy (validated).
__device__ __forceinline__ float fast_tanh(float s) {
    float e = __expf(2.0f * s);
    return 1.0f - __fdividef(2.0f, e + 1.0f);
}

__global__ void __launch_bounds__(THREADS, 2) noise_rnn_kernel(
    const float* __restrict__ x,         // [T,B,I]
    const float* __restrict__ w_ih,      // [H,I]
    const float* __restrict__ w_hh,      // [H,H]
    const float* __restrict__ b_ih,      // [H]
    const float* __restrict__ b_hh,      // [H]
    const float* __restrict__ noise,     // [T,B,H]
    const float* __restrict__ hidden_in, // [1,B,H]
    float* __restrict__ out,             // [T,B,H] (+ [1,B,H] h_last)
    int out_size)
{
    __shared__ __align__(16) float z[KDIM];           // [h(128); x_t(64)]
    __shared__ __align__(16) float psh[NWARPS * HID]; // [warp][j]  (4 KB)

    const int tid   = threadIdx.x;
    const int lane  = tid & 31;
    const int warp  = tid >> 5;
    const int b     = blockIdx.x;      // one batch per block
    const int jbase = lane * 4;        // this thread's 4 output rows
    const int ks    = warp * KSLICE;   // this thread's k-slice start

    // roles
    const bool isRed = (tid < HID);                    // reduce + write z[h]
    const bool isXst = (tid >= HID) && (tid < HID + IN_DIM);  // stage x
    const int  rj    = tid;            // reducer's output row (valid if isRed)
    const int  xi    = tid - HID;      // stager's x index    (valid if isXst)

    // --- W_cat tile in registers, k-pair packed ---
    // W_cat[j][k] = k < HID ? w_hh[j][k] : w_ih[j][k-HID]
    unsigned long long wpk[4][12];
#pragma unroll
    for (int p = 0; p < 12; ++p) {
        const int k0 = ks + 2 * p;
        const int k1 = k0 + 1;
#pragma unroll
        for (int jj = 0; jj < 4; ++jj) {
            const int j = jbase + jj;
            const float lo = (k0 < HID) ? w_hh[j * HID + k0]
                                        : w_ih[j * IN_DIM + (k0 - HID)];
            const float hi = (k1 < HID) ? w_hh[j * HID + k1]
                                        : w_ih[j * IN_DIM + (k1 - HID)];
            wpk[jj][p] = packf2(lo, hi);
        }
    }

    const float bias_r = isRed ? (b_ih[rj] + b_hh[rj]) : 0.0f;

    // --- init z(t=0) = [h0; x0] ---
    if (isRed) z[rj]        = hidden_in[b * HID + rj];
    if (isXst) z[HID + xi]  = x[b * IN_DIM + xi];
    __syncthreads();

    const int noise_base = b * HID + rj;      // reducers
    const int x_base     = b * IN_DIM + xi;   // stagers

    // --- depth-NP prefetch rings: nzbuf[u]=noise[t+u] (reducers), xbuf[u]=x[t+1+u] (stagers) ---
    float nzbuf[NP], xbuf[NP];
#pragma unroll
    for (int u = 0; u < NP; ++u) {
        nzbuf[u] = isRed ? noise[u * (BATCH * HID) + noise_base] : 0.0f;
        xbuf[u]  = (isXst && (u + 1) < T_STEPS)
                   ? x[(u + 1) * (BATCH * IN_DIM) + x_base] : 0.0f;
    }

    for (int t = 0; t < T_STEPS; t += NP) {
#pragma unroll
        for (int u = 0; u < NP; ++u) {
            const int tt = t + u;

            // consume pipelined values, refill for step tt+NP
            const float nz = nzbuf[u];
            const float xn = xbuf[u];
            if (isRed && (tt + NP) < T_STEPS)
                nzbuf[u] = noise[(tt + NP) * (BATCH * HID) + noise_base];
            if (isXst && (tt + NP + 1) < T_STEPS)
                xbuf[u] = x[(tt + NP + 1) * (BATCH * IN_DIM) + x_base];

            // --- matvec partials: 4 j-rows x 24 k, one batch ---
            unsigned long long acc[4] = {0ull, 0ull, 0ull, 0ull};
            const ulonglong2* zq = reinterpret_cast<const ulonglong2*>(z + ks);
#pragma unroll
            for (int q = 0; q < 6; ++q) {
                const ulonglong2 v = zq[q];   // warp-uniform broadcast LDS.128
#pragma unroll
                for (int jj = 0; jj < 4; ++jj) {
                    acc[jj] = fma2(wpk[jj][2 * q],     v.x, acc[jj]);
                    acc[jj] = fma2(wpk[jj][2 * q + 1], v.y, acc[jj]);
                }
            }

            // --- store partials (horizontal add of f32x2 halves), one STS.128 ---
            {
                float4 p0;
                p0.x = lo_f(acc[0]) + hi_f(acc[0]);
                p0.y = lo_f(acc[1]) + hi_f(acc[1]);
                p0.z = lo_f(acc[2]) + hi_f(acc[2]);
                p0.w = lo_f(acc[3]) + hi_f(acc[3]);
                *reinterpret_cast<float4*>(psh + warp * HID + jbase) = p0;
            }
            __syncthreads();

            // --- reduce: thread rj<128 owns output row rj ---
            if (isRed) {
                const float q0 = psh[0 * HID + rj];
                const float q1 = psh[1 * HID + rj];
                const float q2 = psh[2 * HID + rj];
                const float q3 = psh[3 * HID + rj];
                const float q4 = psh[4 * HID + rj];
                const float q5 = psh[5 * HID + rj];
                const float q6 = psh[6 * HID + rj];
                const float q7 = psh[7 * HID + rj];
                const float s = (((q0 + q1) + (q2 + q3)) + ((q4 + q5) + (q6 + q7)))
                              + bias_r;

                const float hn = fast_tanh(s);
                out[tt * (BATCH * HID) + noise_base] = hn;

                const float zn = hn + STD_F * nz;     // noisy carried state
                z[rj] = zn;

                if (tt == T_STEPS - 1 && out_size > T_STEPS * BATCH * HID)
                    out[T_STEPS * (BATCH * HID) + noise_base] = zn;   // h_last
            }
            if (isXst && (tt + 1) < T_STEPS)
                z[HID + xi] = xn;                     // stage next x (parallel role)

            __syncthreads();
        }
    }
}

extern "C" void kernel_launch(void* const* d_in, const int* in_sizes, int n_in,
                              void* d_out, int out_size) {
    const float* x         = (const float*)d_in[0];
    const float* w_ih      = (const float*)d_in[1];
    const float* w_hh      = (const float*)d_in[2];
    const float* b_ih      = (const float*)d_in[3];
    const float* b_hh      = (const float*)d_in[4];
    const float* noise     = (const float*)d_in[5];
    const float* hidden_in = (const float*)d_in[6];
    float* out = (float*)d_out;

    noise_rnn_kernel<<<BATCH, THREADS>>>(x, w_ih, w_hh, b_ih, b_hh,
                                         noise, hidden_in, out, out_size);
}